// round 3
// baseline (speedup 1.0000x reference)
#include <cuda_runtime.h>
#include <cstdint>

#define CC       256
#define HWC      3136
#define NBATCH   32
#define MM       (NBATCH*HWC)   /* 100352 */
#define MT       128
#define NTILES   (MM/MT)        /* 784 */
#define KC       32
#define NCH      (CC/KC)        /* 8 */
#define NTHREADS 512
#define SMEM_BYTES (2*KC*MT*4 + 2*KC*CC*4 + MT*4)  /* 98816 */

// -------------------- device scratch --------------------
__device__ float    g_buf[(size_t)CC*MM];
__device__ float    ut_buf[CC*CC];
__device__ float    chsum_d[CC];
__device__ unsigned gmax_d[CC];
__device__ unsigned gmin_d[CC];
__device__ float    mn_d[CC], s_d[CC], dmin_d[CC], scale_d[CC], inv_d[CC], cvv_d[CC];
__device__ float    qsum_d[CC], bias_d[CC];
__device__ int      same_d[CC];

// -------------------- helpers --------------------
__device__ __forceinline__ unsigned long long pk(float lo, float hi) {
    unsigned long long r;
    asm("mov.b64 %0, {%1,%2};" : "=l"(r) : "f"(lo), "f"(hi));
    return r;
}
__device__ __forceinline__ unsigned long long pk2(float v) { return pk(v, v); }
__device__ __forceinline__ void fma2(unsigned long long& d, unsigned long long a, unsigned long long b) {
    asm("fma.rn.f32x2 %0, %1, %2, %0;" : "+l"(d) : "l"(a), "l"(b));
}
__device__ __forceinline__ void upk(unsigned long long v, float& lo, float& hi) {
    asm("mov.b64 {%0,%1}, %2;" : "=f"(lo), "=f"(hi) : "l"(v));
}
__device__ __forceinline__ void cp16(void* s, const void* g) {
    unsigned sa = (unsigned)__cvta_generic_to_shared(s);
    asm volatile("cp.async.ca.shared.global [%0], [%1], 16;" :: "r"(sa), "l"(g) : "memory");
}
__device__ __forceinline__ void cp_commit() { asm volatile("cp.async.commit_group;" ::: "memory"); }
__device__ __forceinline__ void cp_wait1()  { asm volatile("cp.async.wait_group 1;" ::: "memory"); }
__device__ __forceinline__ void cp_wait0()  { asm volatile("cp.async.wait_group 0;" ::: "memory"); }

// order-preserving float<->uint for atomic max/min
__device__ __forceinline__ unsigned encf(float f) {
    unsigned u = __float_as_uint(f);
    return (u & 0x80000000u) ? ~u : (u | 0x80000000u);
}
__device__ __forceinline__ float decf(unsigned u) {
    unsigned b = (u & 0x80000000u) ? (u & 0x7FFFFFFFu) : ~u;
    return __uint_as_float(b);
}

// -------------------- init --------------------
__global__ void init_k(const float* __restrict__ u) {
    int t = threadIdx.x, b = blockIdx.x;
    if (b == 0) {
        chsum_d[t] = 0.0f; qsum_d[t] = 0.0f;
        gmax_d[t] = 0u;  gmin_d[t] = 0xFFFFFFFFu;
    } else {
        int j = b - 1;
        ut_buf[(size_t)j*CC + t] = u[(size_t)t*CC + j];
    }
}

// -------------------- GEMM (MODE 0: g = u^T relu(x); MODE 1: out = u q + bias) ----
template<int MODE>
__global__ void __launch_bounds__(NTHREADS, 1)
gemm_k(const float* __restrict__ xin, const float* __restrict__ uin, float* __restrict__ og)
{
    extern __shared__ char smem_raw[];
    float* im_s = (float*)smem_raw;                              // [2][KC][MT]
    float* u_s  = (float*)(smem_raw + 2*KC*MT*4);                // [2][KC][CC]
    int*   coff = (int*)  (smem_raw + 2*KC*MT*4 + 2*KC*CC*4);    // [MT]

    const int tid = threadIdx.x;
    const int m0  = blockIdx.x * MT;
    const float* A = MODE ? (const float*)g_buf : xin;
    const float* B = MODE ? (const float*)ut_buf : uin;

    if (tid < MT) {
        int m = m0 + tid;
        int n = m / HWC;
        coff[tid] = n * (CC*HWC) + (m - n*HWC);
    }
    __syncthreads();

    auto stage = [&](int buf, int kc) {
        const int bk = kc * KC;
        float* imd = im_s + buf*(KC*MT);
        float* ud  = u_s  + buf*(KC*CC);
        #pragma unroll
        for (int i = 0; i < 2; i++) {            // 1024 16B units
            int uix = tid + i*NTHREADS;
            int r   = uix >> 5;
            int s4  = (uix & 31) << 2;
            const float* src;
            if (MODE) src = A + (size_t)(bk + r)*MM + (m0 + s4);
            else      src = A + (size_t)coff[s4] + (size_t)(bk + r)*HWC;
            cp16(imd + r*MT + s4, src);
        }
        #pragma unroll
        for (int i = 0; i < 4; i++) {            // 2048 16B units
            int uix = tid + i*NTHREADS;
            int r   = uix >> 6;
            int s4  = (uix & 63) << 2;
            cp16(ud + r*CC + s4, B + (size_t)(bk + r)*CC + s4);
        }
    };

    unsigned long long acc[8][4] = {};   // 8 j x 8 m, packed f32x2
    const int tx = tid & 15;             // m-group
    const int ty = tid >> 4;             // j-group

    stage(0, 0); cp_commit();

    for (int kc = 0; kc < NCH; kc++) {
        const int buf = kc & 1;
        if (kc + 1 < NCH) { stage(buf ^ 1, kc + 1); cp_commit(); cp_wait1(); }
        else              { cp_wait0(); }
        __syncthreads();

        const float* imb = im_s + buf*(KC*MT);
        const float* ub  = u_s  + buf*(KC*CC);

        if (!MODE) {
            // fused channel sums of relu(x)
            int r = tid >> 4;
            const float4* pp = (const float4*)(imb + r*MT + ((tid & 15) << 3));
            float4 v0 = pp[0], v1 = pp[1];
            float sl = fmaxf(v0.x,0.f)+fmaxf(v0.y,0.f)+fmaxf(v0.z,0.f)+fmaxf(v0.w,0.f)
                     + fmaxf(v1.x,0.f)+fmaxf(v1.y,0.f)+fmaxf(v1.z,0.f)+fmaxf(v1.w,0.f);
            sl += __shfl_xor_sync(0xffffffffu, sl, 1);
            sl += __shfl_xor_sync(0xffffffffu, sl, 2);
            sl += __shfl_xor_sync(0xffffffffu, sl, 4);
            sl += __shfl_xor_sync(0xffffffffu, sl, 8);
            if ((tid & 15) == 0) atomicAdd(&chsum_d[kc*KC + r], sl);
        }

        #pragma unroll 8
        for (int k = 0; k < KC; k++) {
            float4 a0 = *(const float4*)(imb + k*MT + tx*8);
            float4 a1 = *(const float4*)(imb + k*MT + tx*8 + 4);
            if (!MODE) {
                a0.x = fmaxf(a0.x, 0.f); a0.y = fmaxf(a0.y, 0.f);
                a0.z = fmaxf(a0.z, 0.f); a0.w = fmaxf(a0.w, 0.f);
                a1.x = fmaxf(a1.x, 0.f); a1.y = fmaxf(a1.y, 0.f);
                a1.z = fmaxf(a1.z, 0.f); a1.w = fmaxf(a1.w, 0.f);
            }
            float4 b0 = *(const float4*)(ub + k*CC + ty*8);
            float4 b1 = *(const float4*)(ub + k*CC + ty*8 + 4);
            unsigned long long Av[4] = { pk(a0.x,a0.y), pk(a0.z,a0.w), pk(a1.x,a1.y), pk(a1.z,a1.w) };
            unsigned long long Bv[8] = { pk2(b0.x), pk2(b0.y), pk2(b0.z), pk2(b0.w),
                                         pk2(b1.x), pk2(b1.y), pk2(b1.z), pk2(b1.w) };
            #pragma unroll
            for (int jj = 0; jj < 8; jj++)
                #pragma unroll
                for (int mm = 0; mm < 4; mm++)
                    fma2(acc[jj][mm], Bv[jj], Av[mm]);
        }
        __syncthreads();
    }

    if (!MODE) {
        #pragma unroll
        for (int jj = 0; jj < 8; jj++) {
            int j = ty*8 + jj;
            float v[8];
            upk(acc[jj][0], v[0], v[1]); upk(acc[jj][1], v[2], v[3]);
            upk(acc[jj][2], v[4], v[5]); upk(acc[jj][3], v[6], v[7]);
            float* dst = g_buf + (size_t)j*MM + m0 + tx*8;
            ((float4*)dst)[0] = make_float4(v[0], v[1], v[2], v[3]);
            ((float4*)dst)[1] = make_float4(v[4], v[5], v[6], v[7]);
            float mx = v[0], mnv = v[0];
            #pragma unroll
            for (int t = 1; t < 8; t++) { mx = fmaxf(mx, v[t]); mnv = fminf(mnv, v[t]); }
            #pragma unroll
            for (int d = 1; d < 16; d <<= 1) {
                mx  = fmaxf(mx,  __shfl_xor_sync(0xffffffffu, mx,  d));
                mnv = fminf(mnv, __shfl_xor_sync(0xffffffffu, mnv, d));
            }
            if (tx == 0) {
                atomicMax(&gmax_d[j], encf(mx));
                atomicMin(&gmin_d[j], encf(mnv));
            }
        }
    } else {
        int cb = coff[tx*8];   // 8-m group never crosses image boundary (3136 % 8 == 0)
        #pragma unroll
        for (int jj = 0; jj < 8; jj++) {
            int c = ty*8 + jj;
            float bb = bias_d[c];
            float v[8];
            upk(acc[jj][0], v[0], v[1]); upk(acc[jj][1], v[2], v[3]);
            upk(acc[jj][2], v[4], v[5]); upk(acc[jj][3], v[6], v[7]);
            float* dst = og + (size_t)cb + (size_t)c*HWC;
            ((float4*)dst)[0] = make_float4(v[0]+bb, v[1]+bb, v[2]+bb, v[3]+bb);
            ((float4*)dst)[1] = make_float4(v[4]+bb, v[5]+bb, v[6]+bb, v[7]+bb);
        }
    }
}

// -------------------- mid: mn, s, dmin/scale per row --------------------
__global__ void mid_k(const float* __restrict__ u, const float* __restrict__ cv,
                      const int* __restrict__ abw) {
    __shared__ float mns[CC];
    int t = threadIdx.x;
    float mn = chsum_d[t] * (1.0f / (float)MM);
    mn_d[t] = mn; mns[t] = mn;
    __syncthreads();
    float s = 0.0f;
    #pragma unroll 8
    for (int c = 0; c < CC; c++) s += u[(size_t)c*CC + t] * mns[c];
    s_d[t] = s;
    float c = cv[t]; cvv_d[t] = c;
    int ab = abw ? *abw : 8;
    float dmax = fminf(fmaxf(decf(gmax_d[t]) - s, -c), c);
    float dmin = fminf(fmaxf(decf(gmin_d[t]) - s, -c), c);
    int same = (dmax == dmin) || (ab >= 17);
    float rng = same ? 1.0f : (dmax - dmin);
    float levels = (float)((1 << (same ? 8 : ab)) - 1);
    same_d[t]  = same;
    dmin_d[t]  = dmin;
    scale_d[t] = levels / rng;
    inv_d[t]   = rng / levels;
}

// -------------------- quantize (in-place on g_buf) --------------------
__global__ void __launch_bounds__(512, 2) quant_k() {
    __shared__ float red[16];
    int j = blockIdx.y;
    size_t base = (size_t)j*MM + (size_t)blockIdx.x*2048 + threadIdx.x*4;
    float s = s_d[j], dmin = dmin_d[j], sc = scale_d[j], inv = inv_d[j], cv = cvv_d[j];
    int same = same_d[j];
    float4 v = *(float4*)(g_buf + base);
    float q[4] = {v.x, v.y, v.z, v.w};
    float sum = 0.0f;
    #pragma unroll
    for (int i = 0; i < 4; i++) {
        float val = fminf(fmaxf(q[i] - s, -cv), cv);
        float qq  = rintf((val - dmin) * sc) * inv + dmin;
        q[i] = same ? val : qq;
        sum += q[i];
    }
    *(float4*)(g_buf + base) = make_float4(q[0], q[1], q[2], q[3]);
    #pragma unroll
    for (int d = 1; d < 32; d <<= 1) sum += __shfl_xor_sync(0xffffffffu, sum, d);
    int lane = threadIdx.x & 31, wid = threadIdx.x >> 5;
    if (lane == 0) red[wid] = sum;
    __syncthreads();
    if (threadIdx.x < 16) {
        float r = red[threadIdx.x];
        #pragma unroll
        for (int d = 1; d < 16; d <<= 1) r += __shfl_xor_sync(0xffffu, r, d);
        if (threadIdx.x == 0) atomicAdd(&qsum_d[j], r);
    }
}

// -------------------- bias --------------------
__global__ void bias_k(const float* __restrict__ u) {
    __shared__ float qm[CC];
    int t = threadIdx.x;
    qm[t] = qsum_d[t] * (1.0f / (float)MM);
    __syncthreads();
    float b = 0.0f;
    #pragma unroll 8
    for (int j = 0; j < CC; j++) b += u[(size_t)t*CC + j] * qm[j];
    bias_d[t] = mn_d[t] - b;
}

// -------------------- launcher --------------------
extern "C" void kernel_launch(void* const* d_in, const int* in_sizes, int n_in,
                              void* d_out, int out_size) {
    const float* x  = (const float*)d_in[0];
    const float* u  = (const float*)d_in[1];
    const float* cv = (const float*)d_in[2];
    const int*   ab = (n_in > 3) ? (const int*)d_in[3] : nullptr;
    float* out = (float*)d_out;
    (void)in_sizes; (void)out_size;

    cudaFuncSetAttribute(gemm_k<0>, cudaFuncAttributeMaxDynamicSharedMemorySize, SMEM_BYTES);
    cudaFuncSetAttribute(gemm_k<1>, cudaFuncAttributeMaxDynamicSharedMemorySize, SMEM_BYTES);

    init_k<<<CC + 1, CC>>>(u);
    gemm_k<0><<<NTILES, NTHREADS, SMEM_BYTES>>>(x, u, nullptr);
    mid_k<<<1, CC>>>(u, cv, ab);
    quant_k<<<dim3(MM/2048, CC), 512>>>();
    bias_k<<<1, CC>>>(u);
    gemm_k<1><<<NTILES, NTHREADS, SMEM_BYTES>>>(nullptr, nullptr, out);
}

// round 5
// speedup vs baseline: 1.0918x; 1.0918x over previous
#include <cuda_runtime.h>
#include <cuda_fp16.h>
#include <cstdint>

#define CC 256
#define HWC 3136
#define MM 100352
#define NTILE 784
#define NTH 256
#define STRA 40                 /* halfs per smem row (80B, conflict-free ldmatrix) */
#define STG_AH 0
#define STG_AM 10240
#define STG_BH 20480
#define STG_BM 30720
#define STG_SZ 40960
#define SO_STG 8192
#define SMEM_T (SO_STG + 2*STG_SZ)   /* 90112 */
#define INV2048 (1.0f/2048.0f)

// -------------------- device scratch --------------------
__device__ __align__(16) float  g_buf[(size_t)CC*MM];
__device__ __align__(16) __half u_hi_d[CC*CC], u_mid_d[CC*CC];
__device__ __align__(16) __half ut_hi_d[CC*CC], ut_mid_d[CC*CC];
__device__ float    chsum_d[CC];
__device__ unsigned gmax_d[CC], gmin_d[CC];
__device__ float    mn_d[CC], s_d[CC], dmin_d[CC], scale_d[CC], inv_d[CC], cvv_d[CC];
__device__ float    qsum_d[CC], bias_d[CC], same_d[CC];

// -------------------- helpers --------------------
__device__ __forceinline__ void cp16(uint32_t sdst, const void* g) {
    asm volatile("cp.async.ca.shared.global [%0], [%1], 16;" :: "r"(sdst), "l"(g) : "memory");
}
__device__ __forceinline__ void cp_commit() { asm volatile("cp.async.commit_group;" ::: "memory"); }
__device__ __forceinline__ void cp_wait0()  { asm volatile("cp.async.wait_group 0;" ::: "memory"); }

__device__ __forceinline__ void ldsm4(unsigned* r, uint32_t addr) {
    asm volatile("ldmatrix.sync.aligned.m8n8.x4.shared.b16 {%0,%1,%2,%3}, [%4];"
        : "=r"(r[0]), "=r"(r[1]), "=r"(r[2]), "=r"(r[3]) : "r"(addr));
}
__device__ __forceinline__ void mma16816(float* d, const unsigned* a, const unsigned* b) {
    asm volatile("mma.sync.aligned.m16n8k16.row.col.f32.f16.f16.f32 "
        "{%0,%1,%2,%3}, {%4,%5,%6,%7}, {%8,%9}, {%0,%1,%2,%3};"
        : "+f"(d[0]), "+f"(d[1]), "+f"(d[2]), "+f"(d[3])
        : "r"(a[0]), "r"(a[1]), "r"(a[2]), "r"(a[3]), "r"(b[0]), "r"(b[1]));
}
__device__ __forceinline__ unsigned encf(float f) {
    unsigned u = __float_as_uint(f);
    return (u & 0x80000000u) ? ~u : (u | 0x80000000u);
}
__device__ __forceinline__ float decf(unsigned u) {
    unsigned b = (u & 0x80000000u) ? (u & 0x7FFFFFFFu) : ~u;
    return __uint_as_float(b);
}
__device__ __forceinline__ float quant1(float g, float s, float dm, float sc, float iv,
                                        float cv, float sm) {
    float val = fminf(fmaxf(g - s, -cv), cv);
    float qq  = rintf((val - dm) * sc) * iv + dm;
    return (sm > 0.5f) ? val : qq;
}

// -------------------- prep: split u into fp16 hi/mid, zero accumulators ----
__global__ void prep_k(const float* __restrict__ u) {
    int t = threadIdx.x, b = blockIdx.x;
    if (b < CC) {
        float val = u[(size_t)b*CC + t];          // u[c=b][j=t]
        __half h = __float2half_rn(val);
        __half e = __float2half_rn((val - __half2float(h)) * 2048.0f);
        u_hi_d [b*CC + t] = h;  u_mid_d [b*CC + t] = e;   // [c][j] for GEMM2 B
        ut_hi_d[t*CC + b] = h;  ut_mid_d[t*CC + b] = e;   // [j][c] for GEMM1 B
    } else {
        chsum_d[t] = 0.0f; qsum_d[t] = 0.0f;
        gmax_d[t] = 0u; gmin_d[t] = 0xFFFFFFFFu;
    }
}

// -------------------- split-fp16 mma.sync GEMM --------------------
// MODE 0: g[j][m] = sum_c relu(x[c,m]) * u[c][j]   (+chsum, per-j max/min)
// MODE 1: out[c][m] = sum_j q(g[j,m]) * u[c][j] + bias[c]   (NCHW scatter)
template<int MODE>
__global__ void __launch_bounds__(NTH)
mgemm_k(const float* __restrict__ X, float* __restrict__ OUT)
{
    extern __shared__ char smem[];
    const uint32_t sb = (uint32_t)__cvta_generic_to_shared(smem);
    const int tid = threadIdx.x;
    const int lane = tid & 31, w = tid >> 5;
    const int m0 = blockIdx.x * 128;
    const int by = blockIdx.y;                 // n-half (0/1)

    float* ps = (float*)smem;                  // 7 param arrays (MODE 1)
    if (MODE) {
        ps[tid]        = s_d[tid];
        ps[256 + tid]  = dmin_d[tid];
        ps[512 + tid]  = scale_d[tid];
        ps[768 + tid]  = inv_d[tid];
        ps[1024 + tid] = cvv_d[tid];
        ps[1280 + tid] = same_d[tid];
        ps[1536 + tid] = bias_d[tid];
        __syncthreads();
    }

    const int mg = tid & 15, cp = tid >> 4;    // producer coords: 8-m group, k-pair
    const int mrow = m0 + mg*8;
    size_t abase = 0;
    if (!MODE) {
        int nimg = mrow / HWC;
        abase = (size_t)nimg*(CC*HWC) + (size_t)(mrow - nimg*HWC);
    }

    float v[2][8];

    auto loadA = [&](int kc) {
        #pragma unroll
        for (int cc = 0; cc < 2; cc++) {
            int c = kc*32 + cp*2 + cc;
            const float4* p;
            if (!MODE) p = (const float4*)(X + abase + (size_t)c*HWC);
            else       p = (const float4*)(g_buf + (size_t)c*MM + mrow);
            float4 q0 = p[0], q1 = p[1];
            v[cc][0]=q0.x; v[cc][1]=q0.y; v[cc][2]=q0.z; v[cc][3]=q0.w;
            v[cc][4]=q1.x; v[cc][5]=q1.y; v[cc][6]=q1.z; v[cc][7]=q1.w;
        }
    };
    auto procA = [&](int kc, int st) {
        char* base = smem + SO_STG + st*STG_SZ;
        #pragma unroll
        for (int cc = 0; cc < 2; cc++) {
            int c = kc*32 + cp*2 + cc;
            if (!MODE) {
                float s = 0.f;
                #pragma unroll
                for (int i = 0; i < 8; i++) { v[cc][i] = fmaxf(v[cc][i], 0.f); s += v[cc][i]; }
                s += __shfl_xor_sync(~0u, s, 1); s += __shfl_xor_sync(~0u, s, 2);
                s += __shfl_xor_sync(~0u, s, 4); s += __shfl_xor_sync(~0u, s, 8);
                if (by == 0 && (lane & 15) == 0) atomicAdd(&chsum_d[c], s);
            } else {
                float S=ps[c], DM=ps[256+c], SC=ps[512+c], IV=ps[768+c],
                      CV=ps[1024+c], SM=ps[1280+c];
                #pragma unroll
                for (int i = 0; i < 8; i++) v[cc][i] = quant1(v[cc][i], S, DM, SC, IV, CV, SM);
            }
        }
        #pragma unroll
        for (int i = 0; i < 8; i++) {
            __half h0 = __float2half_rn(v[0][i]);
            __half h1 = __float2half_rn(v[1][i]);
            __half e0 = __float2half_rn((v[0][i] - __half2float(h0)) * 2048.0f);
            __half e1 = __float2half_rn((v[1][i] - __half2float(h1)) * 2048.0f);
            uint32_t off = (uint32_t)(((mg*8 + i)*STRA + cp*2) * 2);
            *(__half2*)(base + STG_AH + off) = __halves2half2(h0, h1);
            *(__half2*)(base + STG_AM + off) = __halves2half2(e0, e1);
        }
    };
    auto prodB = [&](int kc, int st) {
        const __half* srch = MODE ? u_hi_d  : ut_hi_d;
        const __half* srcm = MODE ? u_mid_d : ut_mid_d;
        #pragma unroll
        for (int i = 0; i < 4; i++) {
            int ui = tid + i*NTH;                 // 0..1023
            int ish = (ui < 512);
            int r = (ui & 511) >> 2;              // row 0..127
            int q = ui & 3;
            uint32_t dst = sb + SO_STG + st*STG_SZ + (ish ? STG_BH : STG_BM)
                         + (uint32_t)(r*80 + q*16);
            const __half* s = (ish ? srch : srcm) + (size_t)(by*128 + r)*CC + kc*32 + q*8;
            cp16(dst, s);
        }
    };

    float acch[2][8][4] = {};
    float accm[2][8][4] = {};
    const int wm = (w & 3) * 32;
    const int wn = (w >> 2) * 64;

    prodB(0, 0); cp_commit();
    loadA(0);
    procA(0, 0);

    const int arow = (lane & 15);
    const int asel = (lane >> 4) << 3;
    const int brow = (lane & 7) + ((lane >> 4) << 3);
    const int bsel = ((lane >> 3) & 1) << 3;

    for (int kc = 0; kc < 8; kc++) {
        const int st = kc & 1;
        if (kc < 7) loadA(kc + 1);
        cp_wait0();
        __syncthreads();

        const uint32_t ahb = sb + SO_STG + st*STG_SZ + STG_AH;
        const uint32_t bhb = sb + SO_STG + st*STG_SZ + STG_BH;
        #pragma unroll
        for (int ks = 0; ks < 2; ks++) {
            const int kb = ks*16;
            unsigned ah[2][4], am[2][4];
            #pragma unroll
            for (int mt = 0; mt < 2; mt++) {
                uint32_t ra = ahb + (uint32_t)(((wm + mt*16 + arow)*STRA + kb + asel) * 2);
                ldsm4(ah[mt], ra);
                ldsm4(am[mt], ra + (STG_AM - STG_AH));
            }
            #pragma unroll
            for (int ng = 0; ng < 4; ng++) {
                uint32_t rb = bhb + (uint32_t)(((wn + ng*16 + brow)*STRA + kb + bsel) * 2);
                unsigned bh[4], bm[4];
                ldsm4(bh, rb);
                ldsm4(bm, rb + (STG_BM - STG_BH));
                #pragma unroll
                for (int mt = 0; mt < 2; mt++) {
                    mma16816(acch[mt][ng*2],     ah[mt], bh);
                    mma16816(acch[mt][ng*2 + 1], ah[mt], bh + 2);
                    mma16816(accm[mt][ng*2],     ah[mt], bm);
                    mma16816(accm[mt][ng*2 + 1], ah[mt], bm + 2);
                    mma16816(accm[mt][ng*2],     am[mt], bh);
                    mma16816(accm[mt][ng*2 + 1], am[mt], bh + 2);
                }
            }
        }
        if (kc < 7) { procA(kc + 1, st ^ 1); prodB(kc + 1, st ^ 1); cp_commit(); }
    }
    __syncthreads();   // stage buffers free -> reuse as transpose scratch

    float* scr = (float*)(smem + SO_STG) + w * (64*36);
    #pragma unroll
    for (int mt = 0; mt < 2; mt++)
        #pragma unroll
        for (int nt = 0; nt < 8; nt++)
            #pragma unroll
            for (int i = 0; i < 4; i++) {
                int nl = nt*8 + (lane & 3)*2 + (i & 1);
                int ml = mt*16 + (lane >> 2) + ((i >> 1) << 3);
                scr[nl*36 + ml] = acch[mt][nt][i] + accm[mt][nt][i] * INV2048;
            }
    __syncwarp();

    if (!MODE) {
        #pragma unroll 4
        for (int r = 0; r < 64; r++) {
            int j = by*128 + wn + r;
            float val = scr[r*36 + lane];
            float mx = val, mn = val;
            #pragma unroll
            for (int d = 1; d < 32; d <<= 1) {
                mx = fmaxf(mx, __shfl_xor_sync(~0u, mx, d));
                mn = fminf(mn, __shfl_xor_sync(~0u, mn, d));
            }
            g_buf[(size_t)j*MM + m0 + wm + lane] = val;
            if (lane == 0) {
                atomicMax(&gmax_d[j], encf(mx));
                atomicMin(&gmin_d[j], encf(mn));
            }
        }
    } else {
        int mstart = m0 + wm;
        int nimg = mstart / HWC;
        size_t base = (size_t)nimg*(CC*HWC) + (size_t)(mstart - nimg*HWC);
        #pragma unroll 4
        for (int r = 0; r < 64; r++) {
            int c = by*128 + wn + r;
            OUT[base + (size_t)c*HWC + lane] = scr[r*36 + lane] + ps[1536 + c];
        }
    }
}

// -------------------- mid: mn, s, clip, quant params --------------------
__global__ void mid_k(const float* __restrict__ u, const float* __restrict__ cv,
                      const int* __restrict__ abw) {
    __shared__ float mns[CC];
    int t = threadIdx.x;
    float mn = chsum_d[t] * (1.0f / (float)MM);
    mn_d[t] = mn; mns[t] = mn;
    __syncthreads();
    float s = 0.0f;
    #pragma unroll 8
    for (int c = 0; c < CC; c++) s += u[(size_t)c*CC + t] * mns[c];
    s_d[t] = s;
    float c = cv[t]; cvv_d[t] = c;
    int ab = abw ? *abw : 8;
    float dmax = fminf(fmaxf(decf(gmax_d[t]) - s, -c), c);
    float dmin = fminf(fmaxf(decf(gmin_d[t]) - s, -c), c);
    int same = (dmax == dmin) || (ab >= 17);
    float rng = same ? 1.0f : (dmax - dmin);
    float levels = (float)((1 << (same ? 8 : ab)) - 1);
    same_d[t]  = same ? 1.0f : 0.0f;
    dmin_d[t]  = dmin;
    scale_d[t] = levels / rng;
    inv_d[t]   = rng / levels;
}

// -------------------- qsum: read-only quant reduction --------------------
__global__ void __launch_bounds__(512, 2) qsum_k() {
    __shared__ float red[16];
    int j = blockIdx.y;
    float s = s_d[j], dm = dmin_d[j], sc = scale_d[j], iv = inv_d[j],
          cv = cvv_d[j], smf = same_d[j];
    size_t base = (size_t)j*MM + (size_t)blockIdx.x*2048 + threadIdx.x*4;
    float4 v = *(const float4*)(g_buf + base);
    float sum = quant1(v.x, s, dm, sc, iv, cv, smf) + quant1(v.y, s, dm, sc, iv, cv, smf)
              + quant1(v.z, s, dm, sc, iv, cv, smf) + quant1(v.w, s, dm, sc, iv, cv, smf);
    #pragma unroll
    for (int d = 1; d < 32; d <<= 1) sum += __shfl_xor_sync(~0u, sum, d);
    int lane = threadIdx.x & 31, wid = threadIdx.x >> 5;
    if (lane == 0) red[wid] = sum;
    __syncthreads();
    if (threadIdx.x < 16) {
        float r = red[threadIdx.x];
        #pragma unroll
        for (int d = 1; d < 16; d <<= 1) r += __shfl_xor_sync(0xffffu, r, d);
        if (threadIdx.x == 0) atomicAdd(&qsum_d[j], r);
    }
}

// -------------------- bias --------------------
__global__ void bias_k(const float* __restrict__ u) {
    __shared__ float qm[CC];
    int t = threadIdx.x;
    qm[t] = qsum_d[t] * (1.0f / (float)MM);
    __syncthreads();
    float b = 0.0f;
    #pragma unroll 8
    for (int j = 0; j < CC; j++) b += u[(size_t)t*CC + j] * qm[j];
    bias_d[t] = mn_d[t] - b;
}

// -------------------- launcher --------------------
extern "C" void kernel_launch(void* const* d_in, const int* in_sizes, int n_in,
                              void* d_out, int out_size) {
    const float* x  = (const float*)d_in[0];
    const float* u  = (const float*)d_in[1];
    const float* cv = (const float*)d_in[2];
    const int*   ab = (n_in > 3) ? (const int*)d_in[3] : nullptr;
    float* out = (float*)d_out;
    (void)in_sizes; (void)out_size;

    cudaFuncSetAttribute(mgemm_k<0>, cudaFuncAttributeMaxDynamicSharedMemorySize, SMEM_T);
    cudaFuncSetAttribute(mgemm_k<1>, cudaFuncAttributeMaxDynamicSharedMemorySize, SMEM_T);

    prep_k<<<CC + 1, CC>>>(u);
    mgemm_k<0><<<dim3(NTILE, 2), NTH, SMEM_T>>>(x, nullptr);
    mid_k<<<1, CC>>>(u, cv, ab);
    qsum_k<<<dim3(MM/2048, CC), 512>>>();
    bias_k<<<1, CC>>>(u);
    mgemm_k<1><<<dim3(NTILE, 2), NTH, SMEM_T>>>(nullptr, out);
}